// round 17
// baseline (speedup 1.0000x reference)
#include <cuda_runtime.h>
#include <cuda_fp16.h>
#include <cstdint>

// GazeLSTM via mma.sync.m16n8k16 fp16. N=256 gate supers, K=272 (x/bias folded).
// R17: B operands read directly from L2 via LDG (warp-coalesced prep layout).
// No cp.async, no B smem, ONE __syncthreads per step. 128 CTAs x 256 thr.

#define LSTEPS 32
#define NCTA   128

#define ABUF   34816                   // 17 ktiles x 2048 B (A frags)
#define SMEM_TOTAL (2 * ABUF)          // 69632

#define GATE_SUP_B 139264              // per gate super: 17s x 4wc x 2048
#define FC_OFF     557056              // 4 * GATE_SUP_B
__device__ __align__(256) uint8_t g_Bu[626688];

__device__ __forceinline__ uint32_t ph2(float a, float b) {
    __half2 h = __floats2half2_rn(a, b);     // .x = a = low 16 bits (even k)
    return *reinterpret_cast<uint32_t*>(&h);
}

__global__ void prep_kernel(const float* __restrict__ W_ih,
                            const float* __restrict__ W_hh,
                            const float* __restrict__ b_ih,
                            const float* __restrict__ b_hh,
                            const float* __restrict__ fc_w,
                            const float* __restrict__ fc_b) {
    int idx = blockIdx.x * blockDim.x + threadIdx.x;
    int stride = gridDim.x * blockDim.x;
    uint32_t* B32 = reinterpret_cast<uint32_t*>(g_Bu);
    // gate supers: u32 idx = (((c*17 + s)*4 + wc)*4 + np)*128 + lane*4 + sub
    for (int e = idx; e < 139264; e += stride) {
        int c = e / 34816, r = e % 34816;
        int s = r >> 11, r2 = r & 2047;
        int wc = r2 >> 9, np = (r2 >> 7) & 3, lane = (r2 >> 2) & 31, sub = r2 & 3;
        int ntp = wc * 4 + np;
        int nt = ntp * 2 + (sub >> 1), reg = sub & 1;
        int nrow = lane >> 2;
        int k0 = s * 16 + (lane & 3) * 2 + reg * 8;
        int wcq = nt >> 3, ntl = nt & 7, jsl = ntl >> 2, q = ntl & 3;
        int grow = q * 256 + c * 64 + wcq * 16 + jsl * 8 + nrow;
        float v[2];
#pragma unroll
        for (int d = 0; d < 2; ++d) {
            int k = k0 + d;
            if (k < 256)       v[d] = W_hh[(size_t)grow * 256 + k];
            else if (k == 256) v[d] = W_ih[grow * 2 + 0];
            else if (k == 257) v[d] = W_ih[grow * 2 + 1];
            else if (k == 258) v[d] = b_ih[grow] + b_hh[grow];
            else               v[d] = 0.0f;
        }
        B32[e] = ph2(v[0], v[1]);
    }
    // FC: u32 idx = (((s*4 + wc)*2 + np)*128 + lane*4 + sub), at FC_OFF
    for (int e = idx; e < 17408; e += stride) {
        int s = e >> 10, r2 = e & 1023;
        int wc = (r2 >> 8) & 3, np = (r2 >> 7) & 1, lane = (r2 >> 2) & 31, sub = r2 & 3;
        int ntp = wc * 2 + np;
        int nt = ntp * 2 + (sub >> 1), reg = sub & 1;
        int o = nt * 8 + (lane >> 2);
        int k0 = s * 16 + (lane & 3) * 2 + reg * 8;
        float v[2];
#pragma unroll
        for (int d = 0; d < 2; ++d) {
            int k = k0 + d;
            if (k < 256)       v[d] = fc_w[(size_t)o * 256 + k];
            else if (k == 258) v[d] = fc_b[o];
            else               v[d] = 0.0f;
        }
        B32[FC_OFF / 4 + e] = ph2(v[0], v[1]);
    }
}

// ---------------- device helpers ----------------
__device__ __forceinline__ uint32_t smem_u32(const void* p) {
    uint32_t a;
    asm("{ .reg .u64 t; cvta.to.shared.u64 t, %1; cvt.u32.u64 %0, t; }" : "=r"(a) : "l"(p));
    return a;
}
__device__ __forceinline__ void mma16816(float (&d)[4], const uint4& a, uint32_t b0, uint32_t b1) {
    asm("mma.sync.aligned.m16n8k16.row.col.f32.f16.f16.f32 "
        "{%0,%1,%2,%3},{%4,%5,%6,%7},{%8,%9},{%0,%1,%2,%3};"
        : "+f"(d[0]), "+f"(d[1]), "+f"(d[2]), "+f"(d[3])
        : "r"(a.x), "r"(a.y), "r"(a.z), "r"(a.w), "r"(b0), "r"(b1));
}
__device__ __forceinline__ float tanha(float x) {
    float r;
    asm("tanh.approx.f32 %0, %1;" : "=f"(r) : "f"(x));
    return r;
}
__device__ __forceinline__ float sigt(float x) {
    return fmaf(tanha(0.5f * x), 0.5f, 0.5f);
}

// gate super: A from smem, B via LDG. Warp tile 2 m-frags x 8 n-tiles.
__device__ __forceinline__ void super_mma_ldg(const uint8_t* sm, uint32_t aoff,
                                              const uint8_t* bg, int wr, int lane,
                                              float (&D)[2][8][4]) {
    const uint8_t* ab = sm + aoff + wr * 1024 + lane * 16;
#pragma unroll
    for (int s = 0; s < 17; ++s) {
        const uint4 A0 = *reinterpret_cast<const uint4*>(ab + s * 2048);
        const uint4 A1 = *reinterpret_cast<const uint4*>(ab + s * 2048 + 512);
        const uint4* bp = reinterpret_cast<const uint4*>(bg + (size_t)s * 8192 + lane * 16);
#pragma unroll
        for (int np = 0; np < 4; ++np) {
            const uint4 B = __ldg(bp + np * 32);    // np*512 bytes
            mma16816(D[0][2 * np],     A0, B.x, B.y);
            mma16816(D[0][2 * np + 1], A0, B.z, B.w);
            mma16816(D[1][2 * np],     A1, B.x, B.y);
            mma16816(D[1][2 * np + 1], A1, B.z, B.w);
        }
    }
}

__device__ __forceinline__ void fc_mma_ldg(const uint8_t* sm, uint32_t aoff,
                                           const uint8_t* bf, int wr, int lane,
                                           float (&D)[2][4][4]) {
    const uint8_t* ab = sm + aoff + wr * 1024 + lane * 16;
#pragma unroll
    for (int s = 0; s < 17; ++s) {
        const uint4 A0 = *reinterpret_cast<const uint4*>(ab + s * 2048);
        const uint4 A1 = *reinterpret_cast<const uint4*>(ab + s * 2048 + 512);
        const uint4* bp = reinterpret_cast<const uint4*>(bf + (size_t)s * 4096 + lane * 16);
#pragma unroll
        for (int np = 0; np < 2; ++np) {
            const uint4 B = __ldg(bp + np * 32);
            mma16816(D[0][2 * np],     A0, B.x, B.y);
            mma16816(D[0][2 * np + 1], A0, B.z, B.w);
            mma16816(D[1][2 * np],     A1, B.x, B.y);
            mma16816(D[1][2 * np + 1], A1, B.z, B.w);
        }
    }
}

// gate epilogue: D -> c,h; h stored as A(pn) fragments (this warp's private slots)
__device__ __forceinline__ void gate_epi(uint8_t* sm, int jb, float (&D)[2][8][4],
                                         float* c_jb, int pn, int wr, int wc, int lane) {
    float h[2][2][4];
#pragma unroll
    for (int mf = 0; mf < 2; ++mf) {
#pragma unroll
        for (int jsl = 0; jsl < 2; ++jsl) {
#pragma unroll
            for (int ci = 0; ci < 4; ++ci) {
                const float gi = D[mf][jsl * 4 + 0][ci];
                const float gf = D[mf][jsl * 4 + 1][ci];
                const float gg = D[mf][jsl * 4 + 2][ci];
                const float go = D[mf][jsl * 4 + 3][ci];
                const int cs = mf * 8 + jsl * 4 + ci;
                const float cn = sigt(gf) * c_jb[cs] + sigt(gi) * tanha(gg);
                c_jb[cs] = cn;
                h[mf][jsl][ci] = sigt(go) * tanha(cn);
            }
        }
    }
    uint8_t* base = sm + pn * ABUF + (size_t)(jb * 4 + wc) * 2048 + wr * 1024 + lane * 16;
#pragma unroll
    for (int mf = 0; mf < 2; ++mf) {
        uint4 v;
        v.x = ph2(h[mf][0][0], h[mf][0][1]);
        v.y = ph2(h[mf][0][2], h[mf][0][3]);
        v.z = ph2(h[mf][1][0], h[mf][1][1]);
        v.w = ph2(h[mf][1][2], h[mf][1][3]);
        *reinterpret_cast<uint4*>(base + mf * 512) = v;
    }
}

__global__ __launch_bounds__(256, 1)
void lstm_kernel(const float* __restrict__ x,     // [8192][32][2]
                 float* __restrict__ out) {       // [8192][32][128]
    extern __shared__ uint8_t sm[];
    const int tx = threadIdx.x;
    const int w = tx >> 5, lane = tx & 31;
    const int wr = w >> 2, wc = w & 3;          // 2 (m) x 4 (n)
    const int g = lane >> 2, t = lane & 3;

    // zero both A bufs
    for (int i = tx; i < 2 * ABUF / 4; i += 256)
        reinterpret_cast<uint32_t*>(sm)[i] = 0u;
    __syncthreads();
    // ones column (k258) in ktile16, both bufs; x_0 into A(0) ktile16
    const int R = blockIdx.x * 64 + wr * 32 + g;
    if (wc == 0 && t == 1) {
        const uint32_t one2 = ph2(1.0f, 0.0f);
#pragma unroll
        for (int p2 = 0; p2 < 2; ++p2)
#pragma unroll
            for (int mf = 0; mf < 2; ++mf)
                *reinterpret_cast<uint4*>(sm + p2 * ABUF + 32768 + wr * 1024 + mf * 512 + lane * 16)
                    = make_uint4(one2, one2, 0u, 0u);
    }
    if (wc == 0 && t == 0) {
#pragma unroll
        for (int mf = 0; mf < 2; ++mf) {
            const int r0 = R + mf * 16;
            const float2 xa = __ldg(reinterpret_cast<const float2*>(x + (size_t)r0 * 64));
            const float2 xb = __ldg(reinterpret_cast<const float2*>(x + (size_t)(r0 + 8) * 64));
            *reinterpret_cast<uint4*>(sm + 32768 + wr * 1024 + mf * 512 + lane * 16)
                = make_uint4(ph2(xa.x, xa.y), ph2(xb.x, xb.y), 0u, 0u);
        }
    }
    __syncthreads();

    float c_st[4][16];
#pragma unroll
    for (int i = 0; i < 4; ++i)
#pragma unroll
        for (int j = 0; j < 16; ++j) c_st[i][j] = 0.0f;

    float D[2][8][4];

#pragma unroll 1
    for (int l = 0; l < LSTEPS; ++l) {
        const int p = l & 1;

        // -------- gates: 4 supers (jb), inline epilogue; no barriers --------
#pragma unroll 1
        for (int jb = 0; jb < 4; ++jb) {
#pragma unroll
            for (int mf = 0; mf < 2; ++mf)
#pragma unroll
                for (int ntl = 0; ntl < 8; ++ntl)
#pragma unroll
                    for (int i = 0; i < 4; ++i) D[mf][ntl][i] = 0.0f;
            const uint8_t* bg = g_Bu + ((size_t)jb * GATE_SUP_B) + (size_t)wc * 2048;
            super_mma_ldg(sm, p * ABUF, bg, wr, lane, D);
            gate_epi(sm, jb, D, c_st[jb], p ^ 1, wr, wc, lane);
        }

        // x_{l+1} into A(p^1) ktile16 (pre-sync; FC's B is zero on k256/257)
        if (l + 1 < LSTEPS && wc == 0 && t == 0) {
#pragma unroll
            for (int mf = 0; mf < 2; ++mf) {
                const int r0 = R + mf * 16;
                const float2 xa = __ldg(reinterpret_cast<const float2*>(x + (size_t)r0 * 64 + (l + 1) * 2));
                const float2 xb = __ldg(reinterpret_cast<const float2*>(x + (size_t)(r0 + 8) * 64 + (l + 1) * 2));
                *reinterpret_cast<uint4*>(sm + (p ^ 1) * ABUF + 32768 + wr * 1024 + mf * 512 + lane * 16)
                    = make_uint4(ph2(xa.x, xa.y), ph2(xb.x, xb.y), 0u, 0u);
            }
        }

        __syncthreads();   // the step's ONLY barrier: publish h_t (+x) fragments

        // -------- FC super (N=128, fc_b folded) on h_t = A(p^1) --------
        {
            float Df[2][4][4];
#pragma unroll
            for (int mf = 0; mf < 2; ++mf)
#pragma unroll
                for (int ntl = 0; ntl < 4; ++ntl)
#pragma unroll
                    for (int i = 0; i < 4; ++i) Df[mf][ntl][i] = 0.0f;
            fc_mma_ldg(sm, (p ^ 1) * ABUF, g_Bu + FC_OFF + (size_t)wc * 1024, wr, lane, Df);
#pragma unroll
            for (int mf = 0; mf < 2; ++mf) {
#pragma unroll
                for (int ntl = 0; ntl < 4; ++ntl) {
                    const int cb = wc * 32 + ntl * 8 + 2 * t;
                    const int rowm = R + mf * 16;
                    *reinterpret_cast<float2*>(out + (size_t)rowm * (LSTEPS * 128) + l * 128 + cb)
                        = make_float2(Df[mf][ntl][0], Df[mf][ntl][1]);
                    *reinterpret_cast<float2*>(out + (size_t)(rowm + 8) * (LSTEPS * 128) + l * 128 + cb)
                        = make_float2(Df[mf][ntl][2], Df[mf][ntl][3]);
                }
            }
        }
    }
}

extern "C" void kernel_launch(void* const* d_in, const int* in_sizes, int n_in,
                              void* d_out, int out_size) {
    const float* x    = (const float*)d_in[0];
    const float* W_ih = (const float*)d_in[1];
    const float* W_hh = (const float*)d_in[2];
    const float* b_ih = (const float*)d_in[3];
    const float* b_hh = (const float*)d_in[4];
    const float* fc_w = (const float*)d_in[5];
    const float* fc_b = (const float*)d_in[6];
    float* out = (float*)d_out;

    prep_kernel<<<288, 256>>>(W_ih, W_hh, b_ih, b_hh, fc_w, fc_b);

    cudaFuncSetAttribute(lstm_kernel, cudaFuncAttributeMaxDynamicSharedMemorySize, SMEM_TOTAL);
    lstm_kernel<<<NCTA, 256, SMEM_TOTAL>>>(x, out);
}